// round 1
// baseline (speedup 1.0000x reference)
#include <cuda_runtime.h>
#include <math.h>

typedef unsigned long long u64;

// ---------------- scratch (device globals; no allocation allowed) ----------
__device__ float4 g_k4[128u * 2048u * 16u];      // k: [B,N,64]  (67MB)
__device__ float4 g_v4[128u * 2048u * 16u];      // v: [B,N,64]  (67MB)
__device__ float4 g_q4[128u * 8u * 16u];         // q: [B,S,64]
__device__ float4 g_attn4[128u * 2048u * 2u];    // attn: [B,N,8] (8.4MB)
__device__ float  g_slots[128 * 8 * 64];
__device__ float  g_colsum[128 * 8];
__device__ float  g_upd[128 * 8 * 64];

// ---------------- packed f32x2 helpers -------------------------------------
__device__ __forceinline__ u64 pk(float lo, float hi) {
    u64 r; asm("mov.b64 %0, {%1, %2};" : "=l"(r) : "f"(lo), "f"(hi)); return r;
}
__device__ __forceinline__ void unpk(u64 v, float& lo, float& hi) {
    asm("mov.b64 {%0, %1}, %2;" : "=f"(lo), "=f"(hi) : "l"(v));
}
__device__ __forceinline__ void fma2(u64& d, u64 a, u64 b) {
    asm("fma.rn.f32x2 %0, %1, %2, %0;" : "+l"(d) : "l"(a), "l"(b));
}

// ===========================================================================
// Kernel 1: fused 1x1 conv -> +bias -> LN(norm) -> LN(ni) -> k = y@Wk^T,
//           v = y@Wv^T. One CTA = 128 pixels of one (batch, src) pair.
// grid (8 ptiles, 2 src, 128 b), block 256.
// dyn smem layout (bytes):
//   [0,16384)       Xs4  float4[32][32]   (phase A)
//   [16384,25088)   Wt   float [32][68]   (phase A)
//   [0,33280)       Ys   float [128][65]  (phase B/C, overlays Xs/Wt)
//   [33280,50688)   Wkt  float [64][68]
//   [50688,68096)   Wvt  float [64][68]
// ===========================================================================
__global__ void conv_ln_kv_kernel(
    const float* __restrict__ x1, const float* __restrict__ x2,
    const float* __restrict__ cw1, const float* __restrict__ cb1,
    const float* __restrict__ cw2, const float* __restrict__ cb2,
    const float* __restrict__ norm_w, const float* __restrict__ norm_b,
    const float* __restrict__ ni_w,  const float* __restrict__ ni_b,
    const float* __restrict__ Wk, const float* __restrict__ Wv)
{
    extern __shared__ char smem[];
    float4* Xs4 = (float4*)smem;                 // [32][32]
    float*  Wt  = (float*)(smem + 16384);        // [32][68]
    float*  Ys  = (float*)smem;                  // [128][65]
    float*  Wkt = (float*)(smem + 33280);        // [64][68]
    float*  Wvt = (float*)(smem + 50688);        // [64][68]

    const int tid = threadIdx.x;
    const int tx = tid & 15;        // pixel group
    const int ty = tid >> 4;        // d group (d = ty*4 + i)
    const int b   = blockIdx.z;
    const int src = blockIdx.y;
    const int p0  = blockIdx.x * 128;

    const float* X    = (src == 0 ? x1 : x2) + (size_t)b * 256 * 1024 + p0;
    const float* W    = (src == 0 ? cw1 : cw2);
    const float* bias = (src == 0 ? cb1 : cb2);

    // Load Wk/Wv transposed once (region disjoint from phase-A buffers).
#pragma unroll
    for (int j = 0; j < 16; ++j) {
        int lin = j * 256 + tid;               // 4096
        int e = lin >> 6, d = lin & 63;        // Wk[e][d]
        Wkt[d * 68 + e] = Wk[lin];
        Wvt[d * 68 + e] = Wv[lin];
    }

    // ---------------- Phase A: conv GEMM (K=256 in 8 chunks of 32) ---------
    u64 acc[4][4];
#pragma unroll
    for (int i = 0; i < 4; ++i)
#pragma unroll
        for (int j = 0; j < 4; ++j) acc[i][j] = 0ull;

    for (int kc = 0; kc < 8; ++kc) {
        __syncthreads();
#pragma unroll
        for (int j = 0; j < 4; ++j) {
            int lin = j * 256 + tid;           // 1024 float4
            int row = lin >> 5, col = lin & 31;
            Xs4[row * 32 + col] =
                ((const float4*)(X + (size_t)(kc * 32 + row) * 1024))[col];
        }
#pragma unroll
        for (int j = 0; j < 8; ++j) {
            int lin = j * 256 + tid;           // 2048
            int d = lin >> 5, cc = lin & 31;
            Wt[cc * 68 + d] = W[d * 256 + kc * 32 + cc];
        }
        __syncthreads();
#pragma unroll
        for (int cc = 0; cc < 32; ++cc) {
            float4 xa = Xs4[cc * 32 + tx];
            float4 xb = Xs4[cc * 32 + 16 + tx];
            float4 w4 = *(const float4*)(Wt + cc * 68 + ty * 4);
            u64 xp0 = pk(xa.x, xa.y), xp1 = pk(xa.z, xa.w);
            u64 xp2 = pk(xb.x, xb.y), xp3 = pk(xb.z, xb.w);
            u64 wp0 = pk(w4.x, w4.x), wp1 = pk(w4.y, w4.y);
            u64 wp2 = pk(w4.z, w4.z), wp3 = pk(w4.w, w4.w);
            fma2(acc[0][0], wp0, xp0); fma2(acc[0][1], wp0, xp1);
            fma2(acc[0][2], wp0, xp2); fma2(acc[0][3], wp0, xp3);
            fma2(acc[1][0], wp1, xp0); fma2(acc[1][1], wp1, xp1);
            fma2(acc[1][2], wp1, xp2); fma2(acc[1][3], wp1, xp3);
            fma2(acc[2][0], wp2, xp0); fma2(acc[2][1], wp2, xp1);
            fma2(acc[2][2], wp2, xp2); fma2(acc[2][3], wp2, xp3);
            fma2(acc[3][0], wp3, xp0); fma2(acc[3][1], wp3, xp1);
            fma2(acc[3][2], wp3, xp2); fma2(acc[3][3], wp3, xp3);
        }
    }

    // ---------------- Phase B: +bias, store to Ys, double LayerNorm --------
    __syncthreads();     // done with Xs/Wt, Ys overlays them
    {
        float bv[4];
#pragma unroll
        for (int i = 0; i < 4; ++i) bv[i] = bias[ty * 4 + i];
#pragma unroll
        for (int i = 0; i < 4; ++i) {
            int d = ty * 4 + i;
#pragma unroll
            for (int j = 0; j < 4; ++j) {
                float lo, hi; unpk(acc[i][j], lo, hi);
                int p = (j < 2) ? (tx * 4 + j * 2) : (64 + tx * 4 + (j - 2) * 2);
                Ys[p * 65 + d]       = lo + bv[i];
                Ys[(p + 1) * 65 + d] = hi + bv[i];
            }
        }
    }
    __syncthreads();

    if (tid < 128) {
        float* row = Ys + tid * 65;
        float s = 0.f, q = 0.f;
#pragma unroll
        for (int d = 0; d < 64; ++d) { float v = row[d]; s += v; q += v * v; }
        float mu = s * (1.f / 64.f);
        float inv = rsqrtf(q * (1.f / 64.f) - mu * mu + 1e-5f);
        s = 0.f; q = 0.f;
#pragma unroll
        for (int d = 0; d < 64; ++d) {
            float y = (row[d] - mu) * inv * norm_w[d] + norm_b[d];
            row[d] = y; s += y; q += y * y;
        }
        mu = s * (1.f / 64.f);
        inv = rsqrtf(q * (1.f / 64.f) - mu * mu + 1e-5f);
#pragma unroll
        for (int d = 0; d < 64; ++d)
            row[d] = (row[d] - mu) * inv * ni_w[d] + ni_b[d];
    }
    __syncthreads();

    // ---------------- Phase C: k = y@Wk^T, v = y@Wv^T ----------------------
    float* kbase = (float*)g_k4 + ((size_t)b * 2048 + src * 1024 + p0) * 64;
    float* vbase = (float*)g_v4 + ((size_t)b * 2048 + src * 1024 + p0) * 64;

    for (int mat = 0; mat < 2; ++mat) {
        const float* Wm = mat ? Wvt : Wkt;
        float* outb = mat ? vbase : kbase;
        u64 a2[4][4];
#pragma unroll
        for (int i = 0; i < 4; ++i)
#pragma unroll
            for (int j = 0; j < 4; ++j) a2[i][j] = 0ull;

        const int pb0 = tx * 4, pb1 = 64 + tx * 4;
#pragma unroll 8
        for (int d = 0; d < 64; ++d) {
            float4 w4 = *(const float4*)(Wm + d * 68 + ty * 4);
            u64 xp0 = pk(Ys[pb0 * 65 + d],       Ys[(pb0 + 1) * 65 + d]);
            u64 xp1 = pk(Ys[(pb0 + 2) * 65 + d], Ys[(pb0 + 3) * 65 + d]);
            u64 xp2 = pk(Ys[pb1 * 65 + d],       Ys[(pb1 + 1) * 65 + d]);
            u64 xp3 = pk(Ys[(pb1 + 2) * 65 + d], Ys[(pb1 + 3) * 65 + d]);
            u64 wp0 = pk(w4.x, w4.x), wp1 = pk(w4.y, w4.y);
            u64 wp2 = pk(w4.z, w4.z), wp3 = pk(w4.w, w4.w);
            fma2(a2[0][0], wp0, xp0); fma2(a2[0][1], wp0, xp1);
            fma2(a2[0][2], wp0, xp2); fma2(a2[0][3], wp0, xp3);
            fma2(a2[1][0], wp1, xp0); fma2(a2[1][1], wp1, xp1);
            fma2(a2[1][2], wp1, xp2); fma2(a2[1][3], wp1, xp3);
            fma2(a2[2][0], wp2, xp0); fma2(a2[2][1], wp2, xp1);
            fma2(a2[2][2], wp2, xp2); fma2(a2[2][3], wp2, xp3);
            fma2(a2[3][0], wp3, xp0); fma2(a2[3][1], wp3, xp1);
            fma2(a2[3][2], wp3, xp2); fma2(a2[3][3], wp3, xp3);
        }
        // store: per ppair j, float4 over d (consecutive in memory)
#pragma unroll
        for (int j = 0; j < 4; ++j) {
            int p = (j < 2) ? (tx * 4 + j * 2) : (64 + tx * 4 + (j - 2) * 2);
            float l0, h0, l1, h1, l2, h2, l3, h3;
            unpk(a2[0][j], l0, h0); unpk(a2[1][j], l1, h1);
            unpk(a2[2][j], l2, h2); unpk(a2[3][j], l3, h3);
            *(float4*)(outb + p * 64 + ty * 4)       = make_float4(l0, l1, l2, l3);
            *(float4*)(outb + (p + 1) * 64 + ty * 4) = make_float4(h0, h1, h2, h3);
        }
    }
}

// ===========================================================================
// Kernel 2: slots = mu + exp(log_sigma) * noise
// ===========================================================================
__global__ void init_slots_kernel(const float* __restrict__ mu,
                                  const float* __restrict__ ls,
                                  const float* __restrict__ noise)
{
    int i = blockIdx.x * 256 + threadIdx.x;   // 65536
    int d = i & 63;
    g_slots[i] = mu[d] + expf(ls[d]) * noise[i];
}

// ===========================================================================
// Kernel 3: q = LN(slots, ns) @ Wq^T * scale; also zero colsum.
// grid B, block 512 (thread = s*64 + d)
// ===========================================================================
__global__ void slot_q_kernel(const float* __restrict__ ns_w,
                              const float* __restrict__ ns_b,
                              const float* __restrict__ Wq)
{
    __shared__ float sn[8][64];
    __shared__ float Wqt[64][65];
    __shared__ float wsum[16], wsq[16];
    const int b = blockIdx.x;
    const int tid = threadIdx.x;
    const int s = tid >> 6, d = tid & 63;

    if (tid < 8) g_colsum[b * 8 + tid] = 0.f;
#pragma unroll
    for (int j = 0; j < 8; ++j) {
        int lin = j * 512 + tid;             // 4096
        int e = lin >> 6, c = lin & 63;      // Wq[e][c]
        Wqt[c][e] = Wq[lin];
    }
    float v = g_slots[(b * 8 + s) * 64 + d];
    float su = v, sq = v * v;
#pragma unroll
    for (int o = 16; o > 0; o >>= 1) {
        su += __shfl_xor_sync(0xffffffffu, su, o);
        sq += __shfl_xor_sync(0xffffffffu, sq, o);
    }
    if ((tid & 31) == 0) { wsum[tid >> 5] = su; wsq[tid >> 5] = sq; }
    __syncthreads();
    float ts = wsum[s * 2] + wsum[s * 2 + 1];
    float tq = wsq[s * 2] + wsq[s * 2 + 1];
    float mu = ts * (1.f / 64.f);
    float inv = rsqrtf(tq * (1.f / 64.f) - mu * mu + 1e-5f);
    sn[s][d] = (v - mu) * inv * ns_w[d] + ns_b[d];
    __syncthreads();
    float acc = 0.f;
#pragma unroll
    for (int c = 0; c < 64; ++c) acc += sn[s][c] * Wqt[c][d];
    ((float*)g_q4)[(b * 8 + s) * 64 + d] = acc * 0.125f;   // D^-0.5
}

// ===========================================================================
// Kernel 4: attn logits + softmax(over S) + eps; column-sum accumulation.
// grid (8, B), block 256. thread = one token n.
// ===========================================================================
__global__ void attn_kernel()
{
    __shared__ float4 qs[8][16];
    __shared__ float csum[8];
    const int b = blockIdx.y;
    const int tid = threadIdx.x;
    const int n = blockIdx.x * 256 + tid;

    if (tid < 128) ((float4*)qs)[tid] = g_q4[b * 128 + tid];
    if (tid < 8) csum[tid] = 0.f;
    __syncthreads();

    const float4* kr = g_k4 + ((size_t)b * 2048 + n) * 16;
    float4 kv[16];
#pragma unroll
    for (int i = 0; i < 16; ++i) kv[i] = kr[i];

    float lg[8];
#pragma unroll
    for (int s = 0; s < 8; ++s) {
        float a = 0.f;
#pragma unroll
        for (int i = 0; i < 16; ++i) {
            float4 q4 = qs[s][i];
            a += kv[i].x * q4.x + kv[i].y * q4.y + kv[i].z * q4.z + kv[i].w * q4.w;
        }
        lg[s] = a;
    }
    float mx = lg[0];
#pragma unroll
    for (int s = 1; s < 8; ++s) mx = fmaxf(mx, lg[s]);
    float sum = 0.f;
#pragma unroll
    for (int s = 0; s < 8; ++s) { lg[s] = __expf(lg[s] - mx); sum += lg[s]; }
    float rinv = 1.f / sum;
#pragma unroll
    for (int s = 0; s < 8; ++s) lg[s] = lg[s] * rinv + 1e-8f;

    float4* ao = g_attn4 + ((size_t)b * 2048 + n) * 2;
    ao[0] = make_float4(lg[0], lg[1], lg[2], lg[3]);
    ao[1] = make_float4(lg[4], lg[5], lg[6], lg[7]);

#pragma unroll
    for (int s = 0; s < 8; ++s) {
        float v = lg[s];
#pragma unroll
        for (int o = 16; o > 0; o >>= 1) v += __shfl_xor_sync(0xffffffffu, v, o);
        if ((tid & 31) == 0) atomicAdd(&csum[s], v);
    }
    __syncthreads();
    if (tid < 8) atomicAdd(&g_colsum[b * 8 + tid], csum[tid]);
}

// ===========================================================================
// Kernel 5: updates[b,s,d] = (1/colsum[b,s]) * sum_n attn[b,n,s]*v[b,n,d]
// grid B, block 512 (thread = s*64 + d)
// ===========================================================================
__global__ void update_kernel()
{
    const int b = blockIdx.x;
    const int tid = threadIdx.x;
    const int s = tid >> 6, d = tid & 63;
    const float* A = (const float*)g_attn4 + (size_t)b * 2048 * 8;
    const float* V = (const float*)g_v4 + (size_t)b * 2048 * 64;
    float acc = 0.f;
#pragma unroll 4
    for (int n = 0; n < 2048; n += 4) {
        acc += A[(n + 0) * 8 + s] * V[(size_t)(n + 0) * 64 + d];
        acc += A[(n + 1) * 8 + s] * V[(size_t)(n + 1) * 64 + d];
        acc += A[(n + 2) * 8 + s] * V[(size_t)(n + 2) * 64 + d];
        acc += A[(n + 3) * 8 + s] * V[(size_t)(n + 3) * 64 + d];
    }
    g_upd[(b * 8 + s) * 64 + d] = acc / g_colsum[b * 8 + s];
}

// ===========================================================================
// Kernel 6: GRUCell + LN(nm) + MLP residual. grid B*S, block 64 (thread = d)
// ===========================================================================
__global__ void gru_mlp_kernel(
    const float* __restrict__ wih, const float* __restrict__ whh,
    const float* __restrict__ bih, const float* __restrict__ bhh,
    const float* __restrict__ nm_w, const float* __restrict__ nm_b,
    const float* __restrict__ w1, const float* __restrict__ b1,
    const float* __restrict__ w2, const float* __restrict__ b2)
{
    const int bs = blockIdx.x;
    const int d = threadIdx.x;
    __shared__ float u[64], sp[64], h[64], h1[128], r4[4];

    u[d]  = g_upd[bs * 64 + d];
    sp[d] = g_slots[bs * 64 + d];
    __syncthreads();

    float gi[3], gh[3];
#pragma unroll
    for (int g = 0; g < 3; ++g) {
        int row = g * 64 + d;
        const float* wi = wih + row * 64;
        const float* wh = whh + row * 64;
        float a = 0.f, c2 = 0.f;
#pragma unroll
        for (int c = 0; c < 64; ++c) { a += u[c] * wi[c]; c2 += sp[c] * wh[c]; }
        gi[g] = a + bih[row];
        gh[g] = c2 + bhh[row];
    }
    float r = 1.f / (1.f + __expf(-(gi[0] + gh[0])));
    float z = 1.f / (1.f + __expf(-(gi[1] + gh[1])));
    float nn = tanhf(gi[2] + r * gh[2]);
    float sl = (1.f - z) * nn + z * sp[d];

    // LN over 64 (2 warps)
    float su = sl, sq = sl * sl;
#pragma unroll
    for (int o = 16; o > 0; o >>= 1) {
        su += __shfl_xor_sync(0xffffffffu, su, o);
        sq += __shfl_xor_sync(0xffffffffu, sq, o);
    }
    if ((d & 31) == 0) { r4[d >> 5] = su; r4[2 + (d >> 5)] = sq; }
    __syncthreads();
    float ts = r4[0] + r4[1], tq = r4[2] + r4[3];
    float mu = ts * (1.f / 64.f);
    float inv = rsqrtf(tq * (1.f / 64.f) - mu * mu + 1e-5f);
    h[d] = (sl - mu) * inv * nm_w[d] + nm_b[d];
    __syncthreads();

    float a0 = b1[d], a1 = b1[64 + d];
    const float* w1a = w1 + d * 64;
    const float* w1b = w1 + (64 + d) * 64;
#pragma unroll
    for (int c = 0; c < 64; ++c) { a0 += h[c] * w1a[c]; a1 += h[c] * w1b[c]; }
    h1[d] = fmaxf(a0, 0.f);
    h1[64 + d] = fmaxf(a1, 0.f);
    __syncthreads();

    float o = b2[d];
    const float* w2r = w2 + d * 128;
#pragma unroll
    for (int j = 0; j < 128; ++j) o += h1[j] * w2r[j];
    g_slots[bs * 64 + d] = sl + o;
}

// ===========================================================================
// Kernel 7: fused = mean(slots, S); out = fused @ head_w^T + head_b
// grid B, block 64
// ===========================================================================
__global__ void head_kernel(const float* __restrict__ head_w,
                            const float* __restrict__ head_b,
                            float* __restrict__ out)
{
    const int b = blockIdx.x;
    const int d = threadIdx.x;
    __shared__ float f[64];
    float a = 0.f;
#pragma unroll
    for (int s = 0; s < 8; ++s) a += g_slots[(b * 8 + s) * 64 + d];
    f[d] = a * 0.125f;
    __syncthreads();
    if (d < 15) {
        float o = head_b[d];
        const float* hw = head_w + d * 64;
#pragma unroll
        for (int c = 0; c < 64; ++c) o += f[c] * hw[c];
        out[b * 15 + d] = o;
    }
}

// ===========================================================================
extern "C" void kernel_launch(void* const* d_in, const int* in_sizes, int n_in,
                              void* d_out, int out_size)
{
    const float* x1      = (const float*)d_in[0];
    const float* x2      = (const float*)d_in[1];
    const float* conv1_w = (const float*)d_in[2];
    const float* conv1_b = (const float*)d_in[3];
    const float* conv2_w = (const float*)d_in[4];
    const float* conv2_b = (const float*)d_in[5];
    const float* norm_w  = (const float*)d_in[6];
    const float* norm_b  = (const float*)d_in[7];
    const float* ni_w    = (const float*)d_in[8];
    const float* ni_b    = (const float*)d_in[9];
    const float* ns_w    = (const float*)d_in[10];
    const float* ns_b    = (const float*)d_in[11];
    const float* nm_w    = (const float*)d_in[12];
    const float* nm_b    = (const float*)d_in[13];
    const float* slots_mu        = (const float*)d_in[14];
    const float* slots_log_sigma = (const float*)d_in[15];
    const float* Wq      = (const float*)d_in[16];
    const float* Wk      = (const float*)d_in[17];
    const float* Wv      = (const float*)d_in[18];
    const float* gru_wih = (const float*)d_in[19];
    const float* gru_whh = (const float*)d_in[20];
    const float* gru_bih = (const float*)d_in[21];
    const float* gru_bhh = (const float*)d_in[22];
    const float* mlp_w1  = (const float*)d_in[23];
    const float* mlp_b1  = (const float*)d_in[24];
    const float* mlp_w2  = (const float*)d_in[25];
    const float* mlp_b2  = (const float*)d_in[26];
    const float* head_w  = (const float*)d_in[27];
    const float* head_b  = (const float*)d_in[28];
    const float* noise   = (const float*)d_in[29];
    float* out = (float*)d_out;

    const int SMEM1 = 68096;
    cudaFuncSetAttribute(conv_ln_kv_kernel,
                         cudaFuncAttributeMaxDynamicSharedMemorySize, SMEM1);

    dim3 g1(8, 2, 128);
    conv_ln_kv_kernel<<<g1, 256, SMEM1>>>(x1, x2, conv1_w, conv1_b,
                                          conv2_w, conv2_b, norm_w, norm_b,
                                          ni_w, ni_b, Wk, Wv);
    init_slots_kernel<<<256, 256>>>(slots_mu, slots_log_sigma, noise);

    for (int it = 0; it < 3; ++it) {
        slot_q_kernel<<<128, 512>>>(ns_w, ns_b, Wq);
        attn_kernel<<<dim3(8, 128), 256>>>();
        update_kernel<<<128, 512>>>();
        gru_mlp_kernel<<<1024, 64>>>(gru_wih, gru_whh, gru_bih, gru_bhh,
                                     nm_w, nm_b, mlp_w1, mlp_b1, mlp_w2, mlp_b2);
    }
    head_kernel<<<128, 64>>>(head_w, head_b, out);
}

// round 3
// speedup vs baseline: 1.2455x; 1.2455x over previous
#include <cuda_runtime.h>
#include <cuda_bf16.h>
#include <cstdint>
#include <math.h>

// ===========================================================================
// Scratch (device globals; no allocation allowed)
// ===========================================================================
__device__ float4 g_k4[128u * 2048u * 16u];      // k: [B,N,64]
__device__ float4 g_v4[128u * 2048u * 16u];      // v: [B,N,64]
__device__ float4 g_q4[128u * 8u * 16u];         // q: [B,S,64]
__device__ float4 g_attn4[128u * 2048u * 2u];    // attn: [B,N,8]
__device__ float  g_slots[128 * 8 * 64];
__device__ float  g_colsum[128 * 8];
__device__ float  g_updp[8 * 128 * 8 * 64];      // partial updates, 8 n-splits

// ===========================================================================
// mma.sync helpers (SM80-style HMMA — portable, works on base sm_103 target)
// ===========================================================================
__device__ __forceinline__ void mma16816(float* c, const uint32_t* a,
                                         uint32_t b0, uint32_t b1) {
    asm volatile(
        "mma.sync.aligned.m16n8k16.row.col.f32.bf16.bf16.f32 "
        "{%0,%1,%2,%3}, {%4,%5,%6,%7}, {%8,%9}, {%0,%1,%2,%3};"
        : "+f"(c[0]), "+f"(c[1]), "+f"(c[2]), "+f"(c[3])
        : "r"(a[0]), "r"(a[1]), "r"(a[2]), "r"(a[3]), "r"(b0), "r"(b1));
}
__device__ __forceinline__ uint32_t lds32(const __nv_bfloat16* p) {
    return *(const uint32_t*)p;
}
__device__ __forceinline__ void cvt_hilo(float x, __nv_bfloat16& h,
                                         __nv_bfloat16& l) {
    h = __float2bfloat16_rn(x);
    l = __float2bfloat16_rn(x - __bfloat162float(h));
}

// smem layout (bytes)
#define SA 138               // A row stride (bf16), k-chunk 128 + pad
#define SW 138               // W row stride
#define SK 70                // Wk/Wv/A2 row stride (K=64 + pad)
#define OFF_A_HI   0u        // 128*138*2 = 35328
#define OFF_A_LO   35328u
#define OFF_W_HI   70656u    // 64*138*2 = 17664
#define OFF_W_LO   88320u
#define OFF_WK_HI  105984u   // 64*70*2 = 8960
#define OFF_WK_LO  114944u
#define OFF_WV_HI  123904u
#define OFF_WV_LO  132864u
#define SM_TOTAL   141824u
// overlays (after conv MMAs complete)
#define OFF_YS     0u        // fp32 [128][65] = 33280 (inside A_HI)
#define OFF_A2_HI  35328u    // 128*70*2 = 17920 (inside A_LO)
#define OFF_A2_LO  53248u    // spills 512B into dead W_HI region — fine

// ===========================================================================
// Kernel 1: fused 1x1 conv GEMM (bf16 2-term HMMA) -> bias -> LN(norm)
//           -> LN(ni) -> k = y@Wk^T, v = y@Wv^T (also HMMA).
// grid (8 ptiles, 2 src, 128 b), block 256 (8 warps; warp w owns rows 16w..)
// ===========================================================================
__global__ __launch_bounds__(256, 1)
void conv_ln_kv_kernel(
    const float* __restrict__ x1, const float* __restrict__ x2,
    const float* __restrict__ cw1, const float* __restrict__ cb1,
    const float* __restrict__ cw2, const float* __restrict__ cb2,
    const float* __restrict__ norm_w, const float* __restrict__ norm_b,
    const float* __restrict__ ni_w,  const float* __restrict__ ni_b,
    const float* __restrict__ Wk, const float* __restrict__ Wv)
{
    extern __shared__ char smem[];
    __nv_bfloat16* Ahi = (__nv_bfloat16*)(smem + OFF_A_HI);
    __nv_bfloat16* Alo = (__nv_bfloat16*)(smem + OFF_A_LO);
    __nv_bfloat16* Whi = (__nv_bfloat16*)(smem + OFF_W_HI);
    __nv_bfloat16* Wlo = (__nv_bfloat16*)(smem + OFF_W_LO);
    __nv_bfloat16* WKhi = (__nv_bfloat16*)(smem + OFF_WK_HI);
    __nv_bfloat16* WKlo = (__nv_bfloat16*)(smem + OFF_WK_LO);
    __nv_bfloat16* WVhi = (__nv_bfloat16*)(smem + OFF_WV_HI);
    __nv_bfloat16* WVlo = (__nv_bfloat16*)(smem + OFF_WV_LO);
    float* Ys = (float*)(smem + OFF_YS);
    __nv_bfloat16* A2hi = (__nv_bfloat16*)(smem + OFF_A2_HI);
    __nv_bfloat16* A2lo = (__nv_bfloat16*)(smem + OFF_A2_LO);

    const int tid = threadIdx.x;
    const int w = tid >> 5, lane = tid & 31;
    const int g = lane >> 2, tg = lane & 3;
    const int r0 = w * 16;
    const int b   = blockIdx.z;
    const int src = blockIdx.y;
    const int p0  = blockIdx.x * 128;

    const float* X    = (src == 0 ? x1 : x2) + (size_t)b * 256 * 1024 + p0;
    const float* W    = (src == 0 ? cw1 : cw2);
    const float* bias = (src == 0 ? cb1 : cb2);

    // ---- Wk/Wv [64,64] -> bf16 hi/lo (row = out n, col = in k) -----------
    {
        int n = tid >> 2, q = tid & 3;        // 4 threads per row, 16 cols each
        const float4* krow = (const float4*)(Wk + n * 64 + q * 16);
        const float4* vrow = (const float4*)(Wv + n * 64 + q * 16);
#pragma unroll
        for (int i = 0; i < 4; ++i) {
            float4 kf = krow[i], vf = vrow[i];
#pragma unroll
            for (int j = 0; j < 4; ++j) {
                int c = q * 16 + i * 4 + j;
                __nv_bfloat16 h, l;
                cvt_hilo((&kf.x)[j], h, l);
                WKhi[n * SK + c] = h; WKlo[n * SK + c] = l;
                cvt_hilo((&vf.x)[j], h, l);
                WVhi[n * SK + c] = h; WVlo[n * SK + c] = l;
            }
        }
    }

    // ---- conv GEMM over 2 K-chunks of 128, accumulators persist ----------
    float acc[8][4];
#pragma unroll
    for (int nf = 0; nf < 8; ++nf)
#pragma unroll
        for (int i = 0; i < 4; ++i) acc[nf][i] = 0.f;

    for (int chunk = 0; chunk < 2; ++chunk) {
        const int cb = chunk * 128;
        __syncthreads();
        // X chunk: [128ch][128px] -> A[p][c] bf16 hi/lo
#pragma unroll 2
        for (int it = 0; it < 16; ++it) {
            int ch = w + 8 * it;
            float4 x4 = *(const float4*)(X + (size_t)(cb + ch) * 1024 + 4 * lane);
#pragma unroll
            for (int i = 0; i < 4; ++i) {
                int p = 4 * lane + i;
                __nv_bfloat16 h, l;
                cvt_hilo((&x4.x)[i], h, l);
                Ahi[p * SA + ch] = h;
                Alo[p * SA + ch] = l;
            }
        }
        // W chunk: [64][128] -> Whi/Wlo
        {
            int n = tid >> 2, q = tid & 3;
#pragma unroll
            for (int i = 0; i < 8; ++i) {
                float4 w4 = *(const float4*)(W + n * 256 + cb + q * 32 + 4 * i);
#pragma unroll
                for (int j = 0; j < 4; ++j) {
                    int c = q * 32 + 4 * i + j;
                    __nv_bfloat16 h, l;
                    cvt_hilo((&w4.x)[j], h, l);
                    Whi[n * SW + c] = h; Wlo[n * SW + c] = l;
                }
            }
        }
        __syncthreads();
        // MMA: 8 k16-steps
#pragma unroll
        for (int ks = 0; ks < 8; ++ks) {
            const int k0 = ks * 16 + 2 * tg;
            uint32_t ah[4], al[4];
            ah[0] = lds32(&Ahi[(r0 + g)     * SA + k0]);
            ah[1] = lds32(&Ahi[(r0 + g + 8) * SA + k0]);
            ah[2] = lds32(&Ahi[(r0 + g)     * SA + k0 + 8]);
            ah[3] = lds32(&Ahi[(r0 + g + 8) * SA + k0 + 8]);
            al[0] = lds32(&Alo[(r0 + g)     * SA + k0]);
            al[1] = lds32(&Alo[(r0 + g + 8) * SA + k0]);
            al[2] = lds32(&Alo[(r0 + g)     * SA + k0 + 8]);
            al[3] = lds32(&Alo[(r0 + g + 8) * SA + k0 + 8]);
#pragma unroll
            for (int nf = 0; nf < 8; ++nf) {
                int n = nf * 8 + g;
                uint32_t bh0 = lds32(&Whi[n * SW + k0]);
                uint32_t bh1 = lds32(&Whi[n * SW + k0 + 8]);
                uint32_t bl0 = lds32(&Wlo[n * SW + k0]);
                uint32_t bl1 = lds32(&Wlo[n * SW + k0 + 8]);
                mma16816(acc[nf], ah, bh0, bh1);
                mma16816(acc[nf], al, bh0, bh1);
                mma16816(acc[nf], ah, bl0, bl1);
            }
        }
    }
    __syncthreads();   // all MMAs done; A_HI region becomes Ys

    // ---- epilogue 1: acc -> Ys (+bias) ------------------------------------
#pragma unroll
    for (int nf = 0; nf < 8; ++nf) {
        int c0 = nf * 8 + 2 * tg;
        float b0 = bias[c0], b1 = bias[c0 + 1];
        Ys[(r0 + g) * 65 + c0]         = acc[nf][0] + b0;
        Ys[(r0 + g) * 65 + c0 + 1]     = acc[nf][1] + b1;
        Ys[(r0 + g + 8) * 65 + c0]     = acc[nf][2] + b0;
        Ys[(r0 + g + 8) * 65 + c0 + 1] = acc[nf][3] + b1;
    }
    __syncthreads();

    // ---- double LayerNorm (one thread per pixel row) ----------------------
    if (tid < 128) {
        float* row = Ys + tid * 65;
        float s = 0.f, q = 0.f;
#pragma unroll
        for (int d = 0; d < 64; ++d) { float v = row[d]; s += v; q += v * v; }
        float mu = s * (1.f / 64.f);
        float inv = rsqrtf(q * (1.f / 64.f) - mu * mu + 1e-5f);
        s = 0.f; q = 0.f;
#pragma unroll
        for (int d = 0; d < 64; ++d) {
            float y = (row[d] - mu) * inv * norm_w[d] + norm_b[d];
            row[d] = y; s += y; q += y * y;
        }
        mu = s * (1.f / 64.f);
        inv = rsqrtf(q * (1.f / 64.f) - mu * mu + 1e-5f);
#pragma unroll
        for (int d = 0; d < 64; ++d)
            row[d] = (row[d] - mu) * inv * ni_w[d] + ni_b[d];
    }
    __syncthreads();

    // ---- Ys -> A2 bf16 hi/lo [128][64] ------------------------------------
#pragma unroll
    for (int j = 0; j < 32; ++j) {
        int lin = j * 256 + tid;             // 8192 elements
        int row = lin >> 6, c = lin & 63;
        __nv_bfloat16 h, l;
        cvt_hilo(Ys[row * 65 + c], h, l);
        A2hi[row * SK + c] = h;
        A2lo[row * SK + c] = l;
    }
    __syncthreads();

    // ---- k/v GEMMs + store -------------------------------------------------
    float* kbase = (float*)g_k4 + ((size_t)b * 2048 + src * 1024 + p0) * 64;
    float* vbase = (float*)g_v4 + ((size_t)b * 2048 + src * 1024 + p0) * 64;

#pragma unroll
    for (int mat = 0; mat < 2; ++mat) {
        const __nv_bfloat16* Bh = mat ? WVhi : WKhi;
        const __nv_bfloat16* Bl = mat ? WVlo : WKlo;
        float* outb = mat ? vbase : kbase;
        float ac[8][4];
#pragma unroll
        for (int nf = 0; nf < 8; ++nf)
#pragma unroll
            for (int i = 0; i < 4; ++i) ac[nf][i] = 0.f;
#pragma unroll
        for (int ks = 0; ks < 4; ++ks) {
            const int k0 = ks * 16 + 2 * tg;
            uint32_t ah[4], al[4];
            ah[0] = lds32(&A2hi[(r0 + g)     * SK + k0]);
            ah[1] = lds32(&A2hi[(r0 + g + 8) * SK + k0]);
            ah[2] = lds32(&A2hi[(r0 + g)     * SK + k0 + 8]);
            ah[3] = lds32(&A2hi[(r0 + g + 8) * SK + k0 + 8]);
            al[0] = lds32(&A2lo[(r0 + g)     * SK + k0]);
            al[1] = lds32(&A2lo[(r0 + g + 8) * SK + k0]);
            al[2] = lds32(&A2lo[(r0 + g)     * SK + k0 + 8]);
            al[3] = lds32(&A2lo[(r0 + g + 8) * SK + k0 + 8]);
#pragma unroll
            for (int nf = 0; nf < 8; ++nf) {
                int n = nf * 8 + g;
                uint32_t bh0 = lds32(&Bh[n * SK + k0]);
                uint32_t bh1 = lds32(&Bh[n * SK + k0 + 8]);
                uint32_t bl0 = lds32(&Bl[n * SK + k0]);
                uint32_t bl1 = lds32(&Bl[n * SK + k0 + 8]);
                mma16816(ac[nf], ah, bh0, bh1);
                mma16816(ac[nf], al, bh0, bh1);
                mma16816(ac[nf], ah, bl0, bl1);
            }
        }
#pragma unroll
        for (int nf = 0; nf < 8; ++nf) {
            int c0 = nf * 8 + 2 * tg;
            *(float2*)(outb + (size_t)(r0 + g) * 64 + c0) =
                make_float2(ac[nf][0], ac[nf][1]);
            *(float2*)(outb + (size_t)(r0 + g + 8) * 64 + c0) =
                make_float2(ac[nf][2], ac[nf][3]);
        }
    }
}

// ===========================================================================
// Kernel 2: slots = mu + exp(log_sigma) * noise
// ===========================================================================
__global__ void init_slots_kernel(const float* __restrict__ mu,
                                  const float* __restrict__ ls,
                                  const float* __restrict__ noise)
{
    int i = blockIdx.x * 256 + threadIdx.x;   // 65536
    int d = i & 63;
    g_slots[i] = mu[d] + expf(ls[d]) * noise[i];
}

// ===========================================================================
// Kernel 3: q = LN(slots, ns) @ Wq^T * scale; zero colsum. grid B, block 512
// ===========================================================================
__global__ void slot_q_kernel(const float* __restrict__ ns_w,
                              const float* __restrict__ ns_b,
                              const float* __restrict__ Wq)
{
    __shared__ float sn[8][64];
    __shared__ float Wqt[64][65];
    __shared__ float wsum[16], wsq[16];
    const int b = blockIdx.x;
    const int tid = threadIdx.x;
    const int s = tid >> 6, d = tid & 63;

    if (tid < 8) g_colsum[b * 8 + tid] = 0.f;
#pragma unroll
    for (int j = 0; j < 8; ++j) {
        int lin = j * 512 + tid;
        int e = lin >> 6, c = lin & 63;
        Wqt[c][e] = Wq[lin];
    }
    float v = g_slots[(b * 8 + s) * 64 + d];
    float su = v, sq = v * v;
#pragma unroll
    for (int o = 16; o > 0; o >>= 1) {
        su += __shfl_xor_sync(0xffffffffu, su, o);
        sq += __shfl_xor_sync(0xffffffffu, sq, o);
    }
    if ((tid & 31) == 0) { wsum[tid >> 5] = su; wsq[tid >> 5] = sq; }
    __syncthreads();
    float ts = wsum[s * 2] + wsum[s * 2 + 1];
    float tq = wsq[s * 2] + wsq[s * 2 + 1];
    float mu = ts * (1.f / 64.f);
    float inv = rsqrtf(tq * (1.f / 64.f) - mu * mu + 1e-5f);
    sn[s][d] = (v - mu) * inv * ns_w[d] + ns_b[d];
    __syncthreads();
    float acc = 0.f;
#pragma unroll
    for (int c = 0; c < 64; ++c) acc += sn[s][c] * Wqt[c][d];
    ((float*)g_q4)[(b * 8 + s) * 64 + d] = acc * 0.125f;
}

// ===========================================================================
// Kernel 4: attn logits + softmax(S) + eps; column sums. grid (8,B), block 256
// ===========================================================================
__global__ void attn_kernel()
{
    __shared__ float qs[8][64];
    __shared__ float csum[8];
    const int b = blockIdx.y;
    const int tid = threadIdx.x;
    const int n = blockIdx.x * 256 + tid;

    ((float*)qs)[tid]       = ((const float*)g_q4)[b * 512 + tid];
    ((float*)qs)[tid + 256] = ((const float*)g_q4)[b * 512 + tid + 256];
    if (tid < 8) csum[tid] = 0.f;
    __syncthreads();

    const float4* kr = g_k4 + ((size_t)b * 2048 + n) * 16;
    float acc[8];
#pragma unroll
    for (int s = 0; s < 8; ++s) acc[s] = 0.f;
#pragma unroll
    for (int i = 0; i < 16; ++i) {
        float4 k4 = kr[i];
#pragma unroll
        for (int s = 0; s < 8; ++s) {
            float4 q4 = *(const float4*)&qs[s][i * 4];
            acc[s] = fmaf(k4.x, q4.x, fmaf(k4.y, q4.y,
                     fmaf(k4.z, q4.z, fmaf(k4.w, q4.w, acc[s]))));
        }
    }
    float mx = acc[0];
#pragma unroll
    for (int s = 1; s < 8; ++s) mx = fmaxf(mx, acc[s]);
    float sum = 0.f;
#pragma unroll
    for (int s = 0; s < 8; ++s) { acc[s] = __expf(acc[s] - mx); sum += acc[s]; }
    float rinv = 1.f / sum;
#pragma unroll
    for (int s = 0; s < 8; ++s) acc[s] = acc[s] * rinv + 1e-8f;

    float4* ao = g_attn4 + ((size_t)b * 2048 + n) * 2;
    ao[0] = make_float4(acc[0], acc[1], acc[2], acc[3]);
    ao[1] = make_float4(acc[4], acc[5], acc[6], acc[7]);

#pragma unroll
    for (int s = 0; s < 8; ++s) {
        float v = acc[s];
#pragma unroll
        for (int o = 16; o > 0; o >>= 1) v += __shfl_xor_sync(0xffffffffu, v, o);
        if ((tid & 31) == 0) atomicAdd(&csum[s], v);
    }
    __syncthreads();
    if (tid < 8) atomicAdd(&g_colsum[b * 8 + tid], csum[tid]);
}

// ===========================================================================
// Kernel 5: partial updates over n-splits (deterministic). grid (B,8), blk 512
// ===========================================================================
__global__ void update_kernel()
{
    const int b = blockIdx.x, sp = blockIdx.y;
    const int tid = threadIdx.x;
    const int s = tid >> 6, d = tid & 63;
    const float* A = (const float*)g_attn4 + ((size_t)b * 2048 + sp * 256) * 8;
    const float* V = (const float*)g_v4 + ((size_t)b * 2048 + sp * 256) * 64;
    float a0 = 0.f, a1 = 0.f;
#pragma unroll 4
    for (int n = 0; n < 256; n += 2) {
        a0 = fmaf(A[n * 8 + s],       V[(size_t)n * 64 + d],       a0);
        a1 = fmaf(A[(n + 1) * 8 + s], V[(size_t)(n + 1) * 64 + d], a1);
    }
    g_updp[sp * 65536 + (b * 8 + s) * 64 + d] = a0 + a1;
}

// ===========================================================================
// Kernel 6: GRUCell + LN(nm) + MLP residual. grid B*S, block 64
// ===========================================================================
__global__ void gru_mlp_kernel(
    const float* __restrict__ wih, const float* __restrict__ whh,
    const float* __restrict__ bih, const float* __restrict__ bhh,
    const float* __restrict__ nm_w, const float* __restrict__ nm_b,
    const float* __restrict__ w1, const float* __restrict__ b1,
    const float* __restrict__ w2, const float* __restrict__ b2)
{
    const int bs = blockIdx.x;
    const int d = threadIdx.x;
    __shared__ float u[64], sp[64], h[64], h1[128], r4[4];

    float uacc = 0.f;
#pragma unroll
    for (int p = 0; p < 8; ++p) uacc += g_updp[p * 65536 + bs * 64 + d];
    u[d]  = uacc / g_colsum[bs];
    sp[d] = g_slots[bs * 64 + d];
    __syncthreads();

    float gi[3], gh[3];
#pragma unroll
    for (int g = 0; g < 3; ++g) {
        int row = g * 64 + d;
        const float* wi = wih + row * 64;
        const float* wh = whh + row * 64;
        float a = 0.f, c2 = 0.f;
#pragma unroll
        for (int c = 0; c < 64; ++c) { a += u[c] * wi[c]; c2 += sp[c] * wh[c]; }
        gi[g] = a + bih[row];
        gh[g] = c2 + bhh[row];
    }
    float r = 1.f / (1.f + __expf(-(gi[0] + gh[0])));
    float z = 1.f / (1.f + __expf(-(gi[1] + gh[1])));
    float nn = tanhf(gi[2] + r * gh[2]);
    float sl = (1.f - z) * nn + z * sp[d];

    float su = sl, sq = sl * sl;
#pragma unroll
    for (int o = 16; o > 0; o >>= 1) {
        su += __shfl_xor_sync(0xffffffffu, su, o);
        sq += __shfl_xor_sync(0xffffffffu, sq, o);
    }
    if ((d & 31) == 0) { r4[d >> 5] = su; r4[2 + (d >> 5)] = sq; }
    __syncthreads();
    float ts = r4[0] + r4[1], tq = r4[2] + r4[3];
    float mu = ts * (1.f / 64.f);
    float inv = rsqrtf(tq * (1.f / 64.f) - mu * mu + 1e-5f);
    h[d] = (sl - mu) * inv * nm_w[d] + nm_b[d];
    __syncthreads();

    float a0 = b1[d], a1 = b1[64 + d];
    const float* w1a = w1 + d * 64;
    const float* w1b = w1 + (64 + d) * 64;
#pragma unroll
    for (int c = 0; c < 64; ++c) { a0 += h[c] * w1a[c]; a1 += h[c] * w1b[c]; }
    h1[d] = fmaxf(a0, 0.f);
    h1[64 + d] = fmaxf(a1, 0.f);
    __syncthreads();

    float o = b2[d];
    const float* w2r = w2 + d * 128;
#pragma unroll
    for (int j = 0; j < 128; ++j) o += h1[j] * w2r[j];
    g_slots[bs * 64 + d] = sl + o;
}

// ===========================================================================
// Kernel 7: fused = mean(slots, S); out = fused @ head_w^T + head_b
// ===========================================================================
__global__ void head_kernel(const float* __restrict__ head_w,
                            const float* __restrict__ head_b,
                            float* __restrict__ out)
{
    const int b = blockIdx.x;
    const int d = threadIdx.x;
    __shared__ float f[64];
    float a = 0.f;
#pragma unroll
    for (int s = 0; s < 8; ++s) a += g_slots[(b * 8 + s) * 64 + d];
    f[d] = a * 0.125f;
    __syncthreads();
    if (d < 15) {
        float o = head_b[d];
        const float* hw = head_w + d * 64;
#pragma unroll
        for (int c = 0; c < 64; ++c) o += f[c] * hw[c];
        out[b * 15 + d] = o;
    }
}

// ===========================================================================
extern "C" void kernel_launch(void* const* d_in, const int* in_sizes, int n_in,
                              void* d_out, int out_size)
{
    const float* x1      = (const float*)d_in[0];
    const float* x2      = (const float*)d_in[1];
    const float* conv1_w = (const float*)d_in[2];
    const float* conv1_b = (const float*)d_in[3];
    const float* conv2_w = (const float*)d_in[4];
    const float* conv2_b = (const float*)d_in[5];
    const float* norm_w  = (const float*)d_in[6];
    const float* norm_b  = (const float*)d_in[7];
    const float* ni_w    = (const float*)d_in[8];
    const float* ni_b    = (const float*)d_in[9];
    const float* ns_w    = (const float*)d_in[10];
    const float* ns_b    = (const float*)d_in[11];
    const float* nm_w    = (const float*)d_in[12];
    const float* nm_b    = (const float*)d_in[13];
    const float* slots_mu        = (const float*)d_in[14];
    const float* slots_log_sigma = (const float*)d_in[15];
    const float* Wq      = (const float*)d_in[16];
    const float* Wk      = (const float*)d_in[17];
    const float* Wv      = (const float*)d_in[18];
    const float* gru_wih = (const float*)d_in[19];
    const float* gru_whh = (const float*)d_in[20];
    const float* gru_bih = (const float*)d_in[21];
    const float* gru_bhh = (const float*)d_in[22];
    const float* mlp_w1  = (const float*)d_in[23];
    const float* mlp_b1  = (const float*)d_in[24];
    const float* mlp_w2  = (const float*)d_in[25];
    const float* mlp_b2  = (const float*)d_in[26];
    const float* head_w  = (const float*)d_in[27];
    const float* head_b  = (const float*)d_in[28];
    const float* noise   = (const float*)d_in[29];
    float* out = (float*)d_out;

    cudaFuncSetAttribute(conv_ln_kv_kernel,
                         cudaFuncAttributeMaxDynamicSharedMemorySize, SM_TOTAL);

    dim3 g1(8, 2, 128);
    conv_ln_kv_kernel<<<g1, 256, SM_TOTAL>>>(x1, x2, conv1_w, conv1_b,
                                             conv2_w, conv2_b, norm_w, norm_b,
                                             ni_w, ni_b, Wk, Wv);
    init_slots_kernel<<<256, 256>>>(slots_mu, slots_log_sigma, noise);

    for (int it = 0; it < 3; ++it) {
        slot_q_kernel<<<128, 512>>>(ns_w, ns_b, Wq);
        attn_kernel<<<dim3(8, 128), 256>>>();
        update_kernel<<<dim3(128, 8), 512>>>();
        gru_mlp_kernel<<<1024, 64>>>(gru_wih, gru_whh, gru_bih, gru_bhh,
                                     nm_w, nm_b, mlp_w1, mlp_b1, mlp_w2, mlp_b2);
    }
    head_kernel<<<128, 64>>>(head_w, head_b, out);
}